// round 1
// baseline (speedup 1.0000x reference)
#include <cuda_runtime.h>
#include <math.h>

#define B_SZ      16
#define DIM       512
#define KEY_DIM   32
#define NUM_HEADS 8
#define RES       1024
#define NH_KD     256      // KEY_DIM * NUM_HEADS
#define D_HEAD    128      // ATTN_RATIO * KEY_DIM
#define DH        1024     // D_HEAD * NUM_HEADS
#define H_QKV     1536     // DH + 2*NH_KD
#define EPS       1e-5f
#define SCALE_QK  0.17677669529663687f   // 32^-0.5

// ---------------- static scratch (no allocs allowed) ----------------
__device__ float g_qkv [B_SZ * H_QKV * RES];                 //  100.7 MB
__device__ float g_q   [B_SZ * NH_KD * RES];                 //   16.8 MB
__device__ float g_attn[134217728];                          //  536.9 MB  (16*8*1024*1024)
__device__ float g_av  [B_SZ * DH * RES];                    //   67.1 MB

// =====================================================================
// Generic 64x64x16 tiled GEMM, C[o][n] = sum_k A[o][k]*B[k][n], BN epilogue.
// 256 threads, 4x4 microtile per thread.
// =====================================================================
template<bool RELU_B>
__device__ __forceinline__ void gemm_body(
    const float* __restrict__ A, const float* __restrict__ Bm, float* __restrict__ C,
    int N, int K, size_t sA, size_t sB, size_t sC,
    const float* __restrict__ gg, const float* __restrict__ bbp,
    const float* __restrict__ mmp, const float* __restrict__ vvp)
{
    __shared__ float As[16][65];   // [k][o], padded
    __shared__ float Bs[16][64];   // [k][n]
    const float* Ab = A  + (size_t)blockIdx.z * sA;
    const float* Bb = Bm + (size_t)blockIdx.z * sB;
    float*       Cb = C  + (size_t)blockIdx.z * sC;

    const int tid = threadIdx.x;
    const int tx = tid & 15, ty = tid >> 4;
    const int row0 = blockIdx.y * 64, col0 = blockIdx.x * 64;

    float acc[4][4] = {};

    for (int k0 = 0; k0 < K; k0 += 16) {
#pragma unroll
        for (int i = 0; i < 4; i++) {
            int idx = tid + i * 256;
            int r  = idx >> 4, c  = idx & 15;
            As[c][r] = Ab[(size_t)(row0 + r) * K + (k0 + c)];
            int r2 = idx >> 6, c2 = idx & 63;
            float vb = Bb[(size_t)(k0 + r2) * N + (col0 + c2)];
            if (RELU_B) vb = fmaxf(vb, 0.0f);
            Bs[r2][c2] = vb;
        }
        __syncthreads();
#pragma unroll
        for (int k = 0; k < 16; k++) {
            float4 bv = *(const float4*)&Bs[k][tx * 4];
            float a0 = As[k][ty * 4 + 0];
            float a1 = As[k][ty * 4 + 1];
            float a2 = As[k][ty * 4 + 2];
            float a3 = As[k][ty * 4 + 3];
            acc[0][0] += a0 * bv.x; acc[0][1] += a0 * bv.y; acc[0][2] += a0 * bv.z; acc[0][3] += a0 * bv.w;
            acc[1][0] += a1 * bv.x; acc[1][1] += a1 * bv.y; acc[1][2] += a1 * bv.z; acc[1][3] += a1 * bv.w;
            acc[2][0] += a2 * bv.x; acc[2][1] += a2 * bv.y; acc[2][2] += a2 * bv.z; acc[2][3] += a2 * bv.w;
            acc[3][0] += a3 * bv.x; acc[3][1] += a3 * bv.y; acc[3][2] += a3 * bv.z; acc[3][3] += a3 * bv.w;
        }
        __syncthreads();
    }

#pragma unroll
    for (int i = 0; i < 4; i++) {
        int o = row0 + ty * 4 + i;
        float inv  = gg[o] * rsqrtf(vvp[o] + EPS);
        float beta = bbp[o] - mmp[o] * inv;
        float4 r;
        r.x = acc[i][0] * inv + beta;
        r.y = acc[i][1] * inv + beta;
        r.z = acc[i][2] * inv + beta;
        r.w = acc[i][3] * inv + beta;
        *(float4*)&Cb[(size_t)o * N + col0 + tx * 4] = r;
    }
}

// K1: qkv = BN(w_qkv @ x)   grid (16, 24, 16)
__global__ void __launch_bounds__(256)
qkv_gemm_kernel(const float* __restrict__ x, const float* __restrict__ w,
                const float* __restrict__ g, const float* __restrict__ b,
                const float* __restrict__ m, const float* __restrict__ v)
{
    gemm_body<false>(w, x, g_qkv, RES, DIM,
                     0, (size_t)DIM * RES, (size_t)H_QKV * RES, g, b, m, v);
}

// K4: out = BN(w_proj @ relu(g_av))   grid (16, 8, 16)
__global__ void __launch_bounds__(256)
proj_gemm_kernel(const float* __restrict__ w, float* __restrict__ out,
                 const float* __restrict__ g, const float* __restrict__ b,
                 const float* __restrict__ m, const float* __restrict__ v)
{
    gemm_body<true>(w, g_av, out, RES, DH,
                    0, (size_t)DH * RES, (size_t)DIM * RES, g, b, m, v);
}

// =====================================================================
// K2: depthwise conv3 (pad 1) over q channels + BN.  grid 16*256 blocks.
// =====================================================================
__global__ void __launch_bounds__(256)
dwconv_kernel(const float* __restrict__ w_dw,
              const float* __restrict__ dg, const float* __restrict__ db,
              const float* __restrict__ dm, const float* __restrict__ dv)
{
    int bc = blockIdx.x;
    int b = bc >> 8, c = bc & 255;
    const float* in  = g_qkv + ((size_t)b * H_QKV + c) * RES;   // q = first 256 channels
    float*       out = g_q   + ((size_t)b * NH_KD + c) * RES;

    __shared__ float s[RES + 2];
    int tid = threadIdx.x;
    for (int i = tid; i < RES; i += 256) s[i + 1] = in[i];
    if (tid == 0) { s[0] = 0.0f; s[RES + 1] = 0.0f; }
    __syncthreads();

    float w0 = w_dw[c * 3 + 0], w1 = w_dw[c * 3 + 1], w2 = w_dw[c * 3 + 2];
    float inv  = dg[c] * rsqrtf(dv[c] + EPS);
    float beta = db[c] - dm[c] * inv;
    for (int i = tid; i < RES; i += 256) {
        float y = w0 * s[i] + w1 * s[i + 1] + w2 * s[i + 2];
        out[i] = y * inv + beta;
    }
}

// =====================================================================
// K3a: S[n][m] = (q.k)*scale + bias[h][|n-m|]   (K=32)  grid (16,16,128)
// =====================================================================
__global__ void __launch_bounds__(256)
scores_kernel(const float* __restrict__ biases)
{
    int bh = blockIdx.z, b = bh >> 3, h = bh & 7;
    const float* Q  = g_q   + ((size_t)b * NH_KD + h * KEY_DIM) * RES;
    const float* Kp = g_qkv + ((size_t)b * H_QKV + NH_KD + h * KEY_DIM) * RES;
    float*       S  = g_attn + (size_t)bh * RES * RES;

    __shared__ float Qs[32][64];
    __shared__ float Ks[32][64];
    int tid = threadIdx.x, tx = tid & 15, ty = tid >> 4;
    int n0 = blockIdx.y * 64, m0 = blockIdx.x * 64;

#pragma unroll
    for (int i = 0; i < 8; i++) {
        int idx = tid + i * 256;
        int d = idx >> 6, c = idx & 63;
        Qs[d][c] = Q [(size_t)d * RES + n0 + c];
        Ks[d][c] = Kp[(size_t)d * RES + m0 + c];
    }
    __syncthreads();

    float acc[4][4] = {};
#pragma unroll
    for (int d = 0; d < 32; d++) {
        float4 kv = *(const float4*)&Ks[d][tx * 4];
        float q0 = Qs[d][ty * 4 + 0];
        float q1 = Qs[d][ty * 4 + 1];
        float q2 = Qs[d][ty * 4 + 2];
        float q3 = Qs[d][ty * 4 + 3];
        acc[0][0] += q0 * kv.x; acc[0][1] += q0 * kv.y; acc[0][2] += q0 * kv.z; acc[0][3] += q0 * kv.w;
        acc[1][0] += q1 * kv.x; acc[1][1] += q1 * kv.y; acc[1][2] += q1 * kv.z; acc[1][3] += q1 * kv.w;
        acc[2][0] += q2 * kv.x; acc[2][1] += q2 * kv.y; acc[2][2] += q2 * kv.z; acc[2][3] += q2 * kv.w;
        acc[3][0] += q3 * kv.x; acc[3][1] += q3 * kv.y; acc[3][2] += q3 * kv.z; acc[3][3] += q3 * kv.w;
    }

    const float* brow = biases + h * RES;
#pragma unroll
    for (int i = 0; i < 4; i++) {
        int n = n0 + ty * 4 + i;
        float4 r;
        int mbase = m0 + tx * 4;
        r.x = acc[i][0] * SCALE_QK + __ldg(&brow[abs(n - (mbase + 0))]);
        r.y = acc[i][1] * SCALE_QK + __ldg(&brow[abs(n - (mbase + 1))]);
        r.z = acc[i][2] * SCALE_QK + __ldg(&brow[abs(n - (mbase + 2))]);
        r.w = acc[i][3] * SCALE_QK + __ldg(&brow[abs(n - (mbase + 3))]);
        *(float4*)&S[(size_t)n * RES + mbase] = r;
    }
}

// =====================================================================
// K3b: row softmax over last dim.  grid = 131072 blocks x 256 thr.
// =====================================================================
__global__ void __launch_bounds__(256)
softmax_kernel()
{
    float* p = g_attn + (size_t)blockIdx.x * RES;
    int tid = threadIdx.x;
    float4 v = ((const float4*)p)[tid];

    __shared__ float shm[8];
    __shared__ float shs[8];

    float mx = fmaxf(fmaxf(v.x, v.y), fmaxf(v.z, v.w));
#pragma unroll
    for (int o = 16; o > 0; o >>= 1) mx = fmaxf(mx, __shfl_xor_sync(0xffffffffu, mx, o));
    if ((tid & 31) == 0) shm[tid >> 5] = mx;
    __syncthreads();
    float m8 = shm[0];
#pragma unroll
    for (int w = 1; w < 8; w++) m8 = fmaxf(m8, shm[w]);

    float e0 = __expf(v.x - m8);
    float e1 = __expf(v.y - m8);
    float e2 = __expf(v.z - m8);
    float e3 = __expf(v.w - m8);
    float s = e0 + e1 + e2 + e3;
#pragma unroll
    for (int o = 16; o > 0; o >>= 1) s += __shfl_xor_sync(0xffffffffu, s, o);
    if ((tid & 31) == 0) shs[tid >> 5] = s;
    __syncthreads();
    float tot = 0.0f;
#pragma unroll
    for (int w = 0; w < 8; w++) tot += shs[w];
    float inv = 1.0f / tot;

    float4 r = make_float4(e0 * inv, e1 * inv, e2 * inv, e3 * inv);
    ((float4*)p)[tid] = r;
}

// =====================================================================
// K3c: O[d][n] = sum_m V[d][m] * P[n][m]   grid (16, 2, 128)
// =====================================================================
__global__ void __launch_bounds__(256)
av_kernel()
{
    int bh = blockIdx.z, b = bh >> 3, h = bh & 7;
    const float* V = g_qkv + ((size_t)b * H_QKV + 2 * NH_KD + h * D_HEAD) * RES;
    const float* P = g_attn + (size_t)bh * RES * RES;
    float*       O = g_av  + ((size_t)b * DH + h * D_HEAD) * RES;

    __shared__ float Vs[16][65];   // [m][d]
    __shared__ float Ps[16][65];   // [m][n]
    int tid = threadIdx.x, tx = tid & 15, ty = tid >> 4;
    int d0 = blockIdx.y * 64, n0 = blockIdx.x * 64;

    float acc[4][4] = {};
    for (int m0 = 0; m0 < RES; m0 += 16) {
#pragma unroll
        for (int i = 0; i < 4; i++) {
            int idx = tid + i * 256;
            int r = idx >> 4, c = idx & 15;
            Vs[c][r] = V[(size_t)(d0 + r) * RES + m0 + c];
            Ps[c][r] = P[(size_t)(n0 + r) * RES + m0 + c];
        }
        __syncthreads();
#pragma unroll
        for (int m = 0; m < 16; m++) {
            float a0 = Vs[m][ty * 4 + 0];
            float a1 = Vs[m][ty * 4 + 1];
            float a2 = Vs[m][ty * 4 + 2];
            float a3 = Vs[m][ty * 4 + 3];
            float p0 = Ps[m][tx * 4 + 0];
            float p1 = Ps[m][tx * 4 + 1];
            float p2 = Ps[m][tx * 4 + 2];
            float p3 = Ps[m][tx * 4 + 3];
            acc[0][0] += a0 * p0; acc[0][1] += a0 * p1; acc[0][2] += a0 * p2; acc[0][3] += a0 * p3;
            acc[1][0] += a1 * p0; acc[1][1] += a1 * p1; acc[1][2] += a1 * p2; acc[1][3] += a1 * p3;
            acc[2][0] += a2 * p0; acc[2][1] += a2 * p1; acc[2][2] += a2 * p2; acc[2][3] += a2 * p3;
            acc[3][0] += a3 * p0; acc[3][1] += a3 * p1; acc[3][2] += a3 * p2; acc[3][3] += a3 * p3;
        }
        __syncthreads();
    }

#pragma unroll
    for (int i = 0; i < 4; i++) {
        int d = d0 + ty * 4 + i;
        float4 r = make_float4(acc[i][0], acc[i][1], acc[i][2], acc[i][3]);
        *(float4*)&O[(size_t)d * RES + n0 + tx * 4] = r;
    }
}

// =====================================================================
extern "C" void kernel_launch(void* const* d_in, const int* in_sizes, int n_in,
                              void* d_out, int out_size)
{
    const float* x       = (const float*)d_in[0];
    const float* w_qkv   = (const float*)d_in[1];
    const float* qkv_g   = (const float*)d_in[2];
    const float* qkv_b   = (const float*)d_in[3];
    const float* qkv_m   = (const float*)d_in[4];
    const float* qkv_v   = (const float*)d_in[5];
    const float* w_dw    = (const float*)d_in[6];
    const float* dw_g    = (const float*)d_in[7];
    const float* dw_b    = (const float*)d_in[8];
    const float* dw_m    = (const float*)d_in[9];
    const float* dw_v    = (const float*)d_in[10];
    const float* w_proj  = (const float*)d_in[11];
    const float* proj_g  = (const float*)d_in[12];
    const float* proj_b  = (const float*)d_in[13];
    const float* proj_m  = (const float*)d_in[14];
    const float* proj_v  = (const float*)d_in[15];
    const float* biases  = (const float*)d_in[16];
    // d_in[17] = bias_idxs (int32) — computed analytically as |n-m|, unused.
    float* out = (float*)d_out;

    // K1: qkv GEMM + BN
    qkv_gemm_kernel<<<dim3(RES / 64, H_QKV / 64, B_SZ), 256>>>(x, w_qkv, qkv_g, qkv_b, qkv_m, qkv_v);
    // K2: depthwise conv + BN on q
    dwconv_kernel<<<B_SZ * NH_KD, 256>>>(w_dw, dw_g, dw_b, dw_m, dw_v);
    // K3a: scores = q^T k * scale + bias
    scores_kernel<<<dim3(RES / 64, RES / 64, B_SZ * NUM_HEADS), 256>>>(biases);
    // K3b: softmax rows
    softmax_kernel<<<B_SZ * NUM_HEADS * RES, 256>>>();
    // K3c: O = V @ P^T
    av_kernel<<<dim3(RES / 64, D_HEAD / 64, B_SZ * NUM_HEADS), 256>>>();
    // K4: proj GEMM (relu on input) + BN
    proj_gemm_kernel<<<dim3(RES / 64, DIM / 64, B_SZ), 256>>>(w_proj, out, proj_g, proj_b, proj_m, proj_v);
}

// round 2
// speedup vs baseline: 1.3476x; 1.3476x over previous
#include <cuda_runtime.h>
#include <math.h>

#define B_SZ      16
#define DIM       512
#define KEY_DIM   32
#define NUM_HEADS 8
#define RES       1024
#define NH_KD     256
#define D_HEAD    128
#define DH        1024
#define H_QKV     1536
#define EPS       1e-5f
#define SCALE_QK  0.17677669529663687f

typedef unsigned long long ull;

// ---------------- static scratch ----------------
__device__ float g_qkv [B_SZ * H_QKV * RES];
__device__ float g_q   [B_SZ * NH_KD * RES];
__device__ float g_attn[134217728];           // 16*8*1024*1024
__device__ float g_av  [B_SZ * DH * RES];

// ---------------- f32x2 packed-FMA helpers ----------------
__device__ __forceinline__ ull pack2(float a) {
    ull r; unsigned ai = __float_as_uint(a);
    asm("mov.b64 %0, {%1, %1};" : "=l"(r) : "r"(ai));
    return r;
}
__device__ __forceinline__ ull ffma2(ull a, ull b, ull c) {
    ull d;
    asm("fma.rn.f32x2 %0, %1, %2, %3;" : "=l"(d) : "l"(a), "l"(b), "l"(c));
    return d;
}
__device__ __forceinline__ float2 unpack2(ull v) {
    float2 f;
    asm("mov.b64 {%0, %1}, %2;" : "=f"(f.x), "=f"(f.y) : "l"(v));
    return f;
}

// ---------------- 16-step packed microkernel ----------------
// As: [16][72] (k-major, padded), Bs: [16][128]
// thread computes rows ty4..ty4+3, cols {tx4..tx4+3, tx4+64..tx4+67}
__device__ __forceinline__ void mma16(const float* __restrict__ As,
                                      const float* __restrict__ Bs,
                                      int ty4, int tx4, ull acc[4][4])
{
#pragma unroll
    for (int k = 0; k < 16; k++) {
        float4 a = *(const float4*)(As + k * 72 + ty4);
        ulonglong2 b0 = *(const ulonglong2*)(Bs + k * 128 + tx4);
        ulonglong2 b1 = *(const ulonglong2*)(Bs + k * 128 + tx4 + 64);
        ull aa;
        aa = pack2(a.x);
        acc[0][0] = ffma2(aa, b0.x, acc[0][0]); acc[0][1] = ffma2(aa, b0.y, acc[0][1]);
        acc[0][2] = ffma2(aa, b1.x, acc[0][2]); acc[0][3] = ffma2(aa, b1.y, acc[0][3]);
        aa = pack2(a.y);
        acc[1][0] = ffma2(aa, b0.x, acc[1][0]); acc[1][1] = ffma2(aa, b0.y, acc[1][1]);
        acc[1][2] = ffma2(aa, b1.x, acc[1][2]); acc[1][3] = ffma2(aa, b1.y, acc[1][3]);
        aa = pack2(a.z);
        acc[2][0] = ffma2(aa, b0.x, acc[2][0]); acc[2][1] = ffma2(aa, b0.y, acc[2][1]);
        acc[2][2] = ffma2(aa, b1.x, acc[2][2]); acc[2][3] = ffma2(aa, b1.y, acc[2][3]);
        aa = pack2(a.w);
        acc[3][0] = ffma2(aa, b0.x, acc[3][0]); acc[3][1] = ffma2(aa, b0.y, acc[3][1]);
        acc[3][2] = ffma2(aa, b1.x, acc[3][2]); acc[3][3] = ffma2(aa, b1.y, acc[3][3]);
    }
}

// =====================================================================
// Generic GEMM+BN: C[o][n] = BN(sum_k A[o][k] * B[k][n]); 64x128 tile.
// =====================================================================
template<bool RELU_B>
__device__ __forceinline__ void gemm_body(
    const float* __restrict__ A, const float* __restrict__ Bm, float* __restrict__ C,
    int N, int K, size_t sB, size_t sC,
    const float* __restrict__ gg, const float* __restrict__ bbp,
    const float* __restrict__ mmp, const float* __restrict__ vvp)
{
    __shared__ float As[16 * 72];
    __shared__ float Bs[16 * 128];
    const float* Bb = Bm + (size_t)blockIdx.z * sB;
    float*       Cb = C  + (size_t)blockIdx.z * sC;

    const int t = threadIdx.x;
    const int ty4 = (t >> 4) * 4;
    const int tx4 = (t & 15) * 4;
    const int row0 = blockIdx.y * 64, col0 = blockIdx.x * 128;

    const int ar  = t >> 2;          // 0..63
    const int akc = (t & 3) * 4;     // 0,4,8,12

    ull acc[4][4] = {};

    for (int k0 = 0; k0 < K; k0 += 16) {
        float4 av = *(const float4*)(A + (size_t)(row0 + ar) * K + k0 + akc);
        As[(akc + 0) * 72 + ar] = av.x;
        As[(akc + 1) * 72 + ar] = av.y;
        As[(akc + 2) * 72 + ar] = av.z;
        As[(akc + 3) * 72 + ar] = av.w;
#pragma unroll
        for (int i = 0; i < 2; i++) {
            int idx = t + 256 * i;
            int kr = idx >> 5;
            int c4 = (idx & 31) * 4;
            float4 bv = *(const float4*)(Bb + (size_t)(k0 + kr) * N + col0 + c4);
            if (RELU_B) {
                bv.x = fmaxf(bv.x, 0.0f); bv.y = fmaxf(bv.y, 0.0f);
                bv.z = fmaxf(bv.z, 0.0f); bv.w = fmaxf(bv.w, 0.0f);
            }
            *(float4*)(Bs + kr * 128 + c4) = bv;
        }
        __syncthreads();
        mma16(As, Bs, ty4, tx4, acc);
        __syncthreads();
    }

#pragma unroll
    for (int i = 0; i < 4; i++) {
        int o = row0 + ty4 + i;
        float inv  = gg[o] * rsqrtf(vvp[o] + EPS);
        float beta = bbp[o] - mmp[o] * inv;
        float2 p0 = unpack2(acc[i][0]), p1 = unpack2(acc[i][1]);
        float2 p2 = unpack2(acc[i][2]), p3 = unpack2(acc[i][3]);
        float4 r0 = make_float4(p0.x * inv + beta, p0.y * inv + beta,
                                p1.x * inv + beta, p1.y * inv + beta);
        float4 r1 = make_float4(p2.x * inv + beta, p2.y * inv + beta,
                                p3.x * inv + beta, p3.y * inv + beta);
        *(float4*)&Cb[(size_t)o * N + col0 + tx4]      = r0;
        *(float4*)&Cb[(size_t)o * N + col0 + tx4 + 64] = r1;
    }
}

__global__ void __launch_bounds__(256)
qkv_gemm_kernel(const float* __restrict__ x, const float* __restrict__ w,
                const float* __restrict__ g, const float* __restrict__ b,
                const float* __restrict__ m, const float* __restrict__ v)
{
    gemm_body<false>(w, x, g_qkv, RES, DIM,
                     (size_t)DIM * RES, (size_t)H_QKV * RES, g, b, m, v);
}

__global__ void __launch_bounds__(256)
proj_gemm_kernel(const float* __restrict__ w, float* __restrict__ out,
                 const float* __restrict__ g, const float* __restrict__ b,
                 const float* __restrict__ m, const float* __restrict__ v)
{
    gemm_body<true>(w, g_av, out, RES, DH,
                    (size_t)DH * RES, (size_t)DIM * RES, g, b, m, v);
}

// =====================================================================
// Depthwise conv3 + BN on q channels.
// =====================================================================
__global__ void __launch_bounds__(256)
dwconv_kernel(const float* __restrict__ w_dw,
              const float* __restrict__ dg, const float* __restrict__ db,
              const float* __restrict__ dm, const float* __restrict__ dv)
{
    int bc = blockIdx.x;
    int b = bc >> 8, c = bc & 255;
    const float* in  = g_qkv + ((size_t)b * H_QKV + c) * RES;
    float*       out = g_q   + ((size_t)b * NH_KD + c) * RES;

    __shared__ float s[RES + 2];
    int tid = threadIdx.x;
    for (int i = tid; i < RES; i += 256) s[i + 1] = in[i];
    if (tid == 0) { s[0] = 0.0f; s[RES + 1] = 0.0f; }
    __syncthreads();

    float w0 = w_dw[c * 3 + 0], w1 = w_dw[c * 3 + 1], w2 = w_dw[c * 3 + 2];
    float inv  = dg[c] * rsqrtf(dv[c] + EPS);
    float beta = db[c] - dm[c] * inv;
    for (int i = tid; i < RES; i += 256) {
        float y = w0 * s[i] + w1 * s[i + 1] + w2 * s[i + 2];
        out[i] = y * inv + beta;
    }
}

// =====================================================================
// Scores: S[n][m] = (q.k)*scale + bias[h][|n-m|].  64(n) x 128(m) tile, K=32.
// =====================================================================
__global__ void __launch_bounds__(256)
scores_kernel(const float* __restrict__ biases)
{
    int bh = blockIdx.z, b = bh >> 3, h = bh & 7;
    const float* Q  = g_q   + ((size_t)b * NH_KD + h * KEY_DIM) * RES;
    const float* Kp = g_qkv + ((size_t)b * H_QKV + NH_KD + h * KEY_DIM) * RES;
    float*       S  = g_attn + (size_t)bh * RES * RES;

    __shared__ float Qs[32 * 72];
    __shared__ float Ks[32 * 128];
    const int t = threadIdx.x;
    const int ty4 = (t >> 4) * 4;
    const int tx4 = (t & 15) * 4;
    const int n0 = blockIdx.y * 64, m0 = blockIdx.x * 128;

#pragma unroll
    for (int i = 0; i < 2; i++) {           // Q tile: 32 x 64
        int idx = t + 256 * i;
        int d = idx >> 4, c4 = (idx & 15) * 4;
        *(float4*)(Qs + d * 72 + c4) = *(const float4*)(Q + (size_t)d * RES + n0 + c4);
    }
#pragma unroll
    for (int i = 0; i < 4; i++) {           // K tile: 32 x 128
        int idx = t + 256 * i;
        int d = idx >> 5, c4 = (idx & 31) * 4;
        *(float4*)(Ks + d * 128 + c4) = *(const float4*)(Kp + (size_t)d * RES + m0 + c4);
    }
    __syncthreads();

    ull acc[4][4] = {};
    mma16(Qs,            Ks,             ty4, tx4, acc);
    mma16(Qs + 16 * 72,  Ks + 16 * 128,  ty4, tx4, acc);

    const float* brow = biases + h * RES;
#pragma unroll
    for (int i = 0; i < 4; i++) {
        int n = n0 + ty4 + i;
        float2 p0 = unpack2(acc[i][0]), p1 = unpack2(acc[i][1]);
        float2 p2 = unpack2(acc[i][2]), p3 = unpack2(acc[i][3]);
        int mb0 = m0 + tx4, mb1 = m0 + tx4 + 64;
        float4 r0, r1;
        r0.x = p0.x * SCALE_QK + __ldg(&brow[abs(n - (mb0 + 0))]);
        r0.y = p0.y * SCALE_QK + __ldg(&brow[abs(n - (mb0 + 1))]);
        r0.z = p1.x * SCALE_QK + __ldg(&brow[abs(n - (mb0 + 2))]);
        r0.w = p1.y * SCALE_QK + __ldg(&brow[abs(n - (mb0 + 3))]);
        r1.x = p2.x * SCALE_QK + __ldg(&brow[abs(n - (mb1 + 0))]);
        r1.y = p2.y * SCALE_QK + __ldg(&brow[abs(n - (mb1 + 1))]);
        r1.z = p3.x * SCALE_QK + __ldg(&brow[abs(n - (mb1 + 2))]);
        r1.w = p3.y * SCALE_QK + __ldg(&brow[abs(n - (mb1 + 3))]);
        *(float4*)&S[(size_t)n * RES + mb0] = r0;
        *(float4*)&S[(size_t)n * RES + mb1] = r1;
    }
}

// =====================================================================
// Row softmax.
// =====================================================================
__global__ void __launch_bounds__(256)
softmax_kernel()
{
    float* p = g_attn + (size_t)blockIdx.x * RES;
    int tid = threadIdx.x;
    float4 v = ((const float4*)p)[tid];

    __shared__ float shm[8];
    __shared__ float shs[8];

    float mx = fmaxf(fmaxf(v.x, v.y), fmaxf(v.z, v.w));
#pragma unroll
    for (int o = 16; o > 0; o >>= 1) mx = fmaxf(mx, __shfl_xor_sync(0xffffffffu, mx, o));
    if ((tid & 31) == 0) shm[tid >> 5] = mx;
    __syncthreads();
    float m8 = shm[0];
#pragma unroll
    for (int w = 1; w < 8; w++) m8 = fmaxf(m8, shm[w]);

    float e0 = __expf(v.x - m8);
    float e1 = __expf(v.y - m8);
    float e2 = __expf(v.z - m8);
    float e3 = __expf(v.w - m8);
    float s = e0 + e1 + e2 + e3;
#pragma unroll
    for (int o = 16; o > 0; o >>= 1) s += __shfl_xor_sync(0xffffffffu, s, o);
    if ((tid & 31) == 0) shs[tid >> 5] = s;
    __syncthreads();
    float tot = 0.0f;
#pragma unroll
    for (int w = 0; w < 8; w++) tot += shs[w];
    float inv = 1.0f / tot;

    ((float4*)p)[tid] = make_float4(e0 * inv, e1 * inv, e2 * inv, e3 * inv);
}

// =====================================================================
// AV: O[d][n] = sum_m V[d][m] * P[n][m].  64(d) x 128(n) tile.
// =====================================================================
__global__ void __launch_bounds__(256)
av_kernel()
{
    int bh = blockIdx.z, b = bh >> 3, h = bh & 7;
    const float* V = g_qkv + ((size_t)b * H_QKV + 2 * NH_KD + h * D_HEAD) * RES;
    const float* P = g_attn + (size_t)bh * RES * RES;
    float*       O = g_av  + ((size_t)b * DH + h * D_HEAD) * RES;

    __shared__ float Vs[16 * 72];    // [m][d]
    __shared__ float Ps[16 * 128];   // [m][n]
    const int t = threadIdx.x;
    const int ty4 = (t >> 4) * 4;
    const int tx4 = (t & 15) * 4;
    const int d0 = blockIdx.y * 64, n0 = blockIdx.x * 128;

    const int ar  = t >> 2;        // d row 0..63
    const int akc = (t & 3) * 4;   // m chunk

    ull acc[4][4] = {};

    for (int m0 = 0; m0 < RES; m0 += 16) {
        float4 vv = *(const float4*)(V + (size_t)(d0 + ar) * RES + m0 + akc);
        Vs[(akc + 0) * 72 + ar] = vv.x;
        Vs[(akc + 1) * 72 + ar] = vv.y;
        Vs[(akc + 2) * 72 + ar] = vv.z;
        Vs[(akc + 3) * 72 + ar] = vv.w;
#pragma unroll
        for (int i = 0; i < 2; i++) {
            int idx = t + 256 * i;
            int n  = idx >> 2;            // 0..127
            int mc = (idx & 3) * 4;
            float4 pv = *(const float4*)(P + (size_t)(n0 + n) * RES + m0 + mc);
            Ps[(mc + 0) * 128 + n] = pv.x;
            Ps[(mc + 1) * 128 + n] = pv.y;
            Ps[(mc + 2) * 128 + n] = pv.z;
            Ps[(mc + 3) * 128 + n] = pv.w;
        }
        __syncthreads();
        mma16(Vs, Ps, ty4, tx4, acc);
        __syncthreads();
    }

#pragma unroll
    for (int i = 0; i < 4; i++) {
        int d = d0 + ty4 + i;
        float2 p0 = unpack2(acc[i][0]), p1 = unpack2(acc[i][1]);
        float2 p2 = unpack2(acc[i][2]), p3 = unpack2(acc[i][3]);
        *(float4*)&O[(size_t)d * RES + n0 + tx4]      = make_float4(p0.x, p0.y, p1.x, p1.y);
        *(float4*)&O[(size_t)d * RES + n0 + tx4 + 64] = make_float4(p2.x, p2.y, p3.x, p3.y);
    }
}

// =====================================================================
extern "C" void kernel_launch(void* const* d_in, const int* in_sizes, int n_in,
                              void* d_out, int out_size)
{
    const float* x       = (const float*)d_in[0];
    const float* w_qkv   = (const float*)d_in[1];
    const float* qkv_g   = (const float*)d_in[2];
    const float* qkv_b   = (const float*)d_in[3];
    const float* qkv_m   = (const float*)d_in[4];
    const float* qkv_v   = (const float*)d_in[5];
    const float* w_dw    = (const float*)d_in[6];
    const float* dw_g    = (const float*)d_in[7];
    const float* dw_b    = (const float*)d_in[8];
    const float* dw_m    = (const float*)d_in[9];
    const float* dw_v    = (const float*)d_in[10];
    const float* w_proj  = (const float*)d_in[11];
    const float* proj_g  = (const float*)d_in[12];
    const float* proj_b  = (const float*)d_in[13];
    const float* proj_m  = (const float*)d_in[14];
    const float* proj_v  = (const float*)d_in[15];
    const float* biases  = (const float*)d_in[16];
    float* out = (float*)d_out;

    qkv_gemm_kernel<<<dim3(RES / 128, H_QKV / 64, B_SZ), 256>>>(x, w_qkv, qkv_g, qkv_b, qkv_m, qkv_v);
    dwconv_kernel<<<B_SZ * NH_KD, 256>>>(w_dw, dw_g, dw_b, dw_m, dw_v);
    scores_kernel<<<dim3(RES / 128, RES / 64, B_SZ * NUM_HEADS), 256>>>(biases);
    softmax_kernel<<<B_SZ * NUM_HEADS * RES, 256>>>();
    av_kernel<<<dim3(RES / 128, D_HEAD / 64, B_SZ * NUM_HEADS), 256>>>();
    proj_gemm_kernel<<<dim3(RES / 128, DIM / 64, B_SZ), 256>>>(w_proj, out, proj_g, proj_b, proj_m, proj_v);
}